// round 9
// baseline (speedup 1.0000x reference)
#include <cuda_runtime.h>
#include <cuda_bf16.h>
#include <cuda_fp8.h>
#include <cstdint>

#define B_    2
#define S_    2048
#define DM    1024
#define H_    16
#define HD    64
#define MROWS 4096
#define XN    (MROWS * DM)      // 4194304
#define WN    (DM * DM)         // 1048576

typedef unsigned long long u64;
typedef unsigned int u32;
typedef unsigned char u8;
typedef unsigned short u16;

// ---------------- scratch (device globals; no allocation allowed) ----------------
__device__ __align__(16) u8   g_x8[XN];                   // x in e4m3 (4 MB)
__device__ __align__(16) u8   g_w8[3 * WN];               // wq|wk|wv e4m3 (3 MB)
__device__ __align__(16) u8   g_wo8[WN];                  // wo e4m3 (1 MB)
__device__ __align__(16) u64  g_qbits[B_ * H_ * S_];      // packed Q bits
__device__ __align__(16) u64  g_kbits[B_ * H_ * S_];      // packed K bits
__device__ __align__(16) __nv_bfloat16 g_vb[B_ * H_ * S_ * HD]; // V head-major bf16 (8 MB)
__device__ __align__(16) u8   g_attn8[XN];                // attention out e4m3 (4 MB)

// ---------------- helpers ----------------
__device__ __forceinline__ u32 smem_u32(const void* p) {
    u32 a;
    asm("{ .reg .u64 t; cvta.to.shared.u64 t, %1; cvt.u32.u64 %0, t; }" : "=r"(a) : "l"(p));
    return a;
}
__device__ __forceinline__ void cp16(u32 saddr, const void* gaddr) {
    asm volatile("cp.async.cg.shared.global [%0], [%1], 16;" :: "r"(saddr), "l"(gaddr));
}
__device__ __forceinline__ void cp_commit() { asm volatile("cp.async.commit_group;" ::: "memory"); }
template <int N> __device__ __forceinline__ void cp_wait() {
    asm volatile("cp.async.wait_group %0;" :: "n"(N) : "memory");
}
__device__ __forceinline__ void ldsm_x4(u32* r, u32 addr) {
    asm volatile("ldmatrix.sync.aligned.m8n8.x4.shared.b16 {%0,%1,%2,%3}, [%4];"
        : "=r"(r[0]), "=r"(r[1]), "=r"(r[2]), "=r"(r[3]) : "r"(addr));
}
__device__ __forceinline__ void ldsm_x4_t(u32* r, u32 addr) {
    asm volatile("ldmatrix.sync.aligned.m8n8.x4.trans.shared.b16 {%0,%1,%2,%3}, [%4];"
        : "=r"(r[0]), "=r"(r[1]), "=r"(r[2]), "=r"(r[3]) : "r"(addr));
}
__device__ __forceinline__ void mma16816(float* c, const u32* a, const u32* b) {
    asm volatile("mma.sync.aligned.m16n8k16.row.col.f32.bf16.bf16.f32 "
        "{%0,%1,%2,%3}, {%4,%5,%6,%7}, {%8,%9}, {%0,%1,%2,%3};"
        : "+f"(c[0]), "+f"(c[1]), "+f"(c[2]), "+f"(c[3])
        : "r"(a[0]), "r"(a[1]), "r"(a[2]), "r"(a[3]), "r"(b[0]), "r"(b[1]));
}
__device__ __forceinline__ void mma16832_fp8(float* c, const u32* a, const u32* b) {
    asm volatile("mma.sync.aligned.m16n8k32.row.col.f32.e4m3.e4m3.f32 "
        "{%0,%1,%2,%3}, {%4,%5,%6,%7}, {%8,%9}, {%0,%1,%2,%3};"
        : "+f"(c[0]), "+f"(c[1]), "+f"(c[2]), "+f"(c[3])
        : "r"(a[0]), "r"(a[1]), "r"(a[2]), "r"(a[3]), "r"(b[0]), "r"(b[1]));
}
__device__ __forceinline__ float ex2(float x) {
    float y; asm("ex2.approx.ftz.f32 %0, %1;" : "=f"(y) : "f"(x)); return y;
}
__device__ __forceinline__ u32 bf2pack(float a, float b) {
    __nv_bfloat162 t = __floats2bfloat162_rn(a, b);
    return *(u32*)&t;
}
__device__ __forceinline__ u8 f2e4m3(float x) {
    return (u8)__nv_cvt_float_to_fp8(x, __NV_SATFINITE, __NV_E4M3);
}
#define SW128(o) ((o) ^ ((((u32)(o)) >> 3) & 0x70))

// ---------------- fp32 -> e4m3 conversion of x and all weights ----------------
__global__ void __launch_bounds__(256) convert_kernel(const float* __restrict__ x,
                                                      const float* __restrict__ wq,
                                                      const float* __restrict__ wk,
                                                      const float* __restrict__ wv,
                                                      const float* __restrict__ wo) {
    size_t i = ((size_t)blockIdx.x * blockDim.x + threadIdx.x) * 4;
    const float* src;
    u8* dst;
    size_t off;
    if (i < XN) { src = x; dst = g_x8; off = i; }
    else {
        size_t j = i - XN;
        int w = (int)(j >> 20);
        off = j & (WN - 1);
        src = (w == 0) ? wq : (w == 1) ? wk : (w == 2) ? wv : wo;
        dst = (w < 3) ? (g_w8 + (size_t)w * WN) : g_wo8;
    }
    float4 v = *(const float4*)(src + off);
    u32 pk = (u32)f2e4m3(v.x) | ((u32)f2e4m3(v.y) << 8)
           | ((u32)f2e4m3(v.z) << 16) | ((u32)f2e4m3(v.w) << 24);
    *(u32*)(dst + off) = pk;
}

// ---------------- FP8 HMMA GEMM: C = threshold(A @ W^T + bias), 3-stage cp.async ----------------
// MODE 0: A=g_x8, W=g_w8 (3072 N-rows: q|k|v), epilogue -> g_qbits/g_kbits masks, g_vb bf16
// MODE 1: A=g_attn8, W=g_wo8, epilogue -> out fp32 {0,1}
// CTA tile M=128 N=128, 8 warps as 4(m) x 2(n). K chunks of 128 e4m3 (128B rows), 8 chunks.
template <int MODE>
__global__ void __launch_bounds__(256) gemm_mma(const float* __restrict__ bb0,
                                               const float* __restrict__ bb1,
                                               const float* __restrict__ bb2,
                                               float* __restrict__ out) {
    __shared__ __align__(16) u8 As[3][128 * 128];   // 3 x 16 KB
    __shared__ __align__(16) u8 Bs[3][128 * 128];   // 3 x 16 KB
    __shared__ float sbias[128];

    const int tid = threadIdx.x, lane = tid & 31, wid = tid >> 5;
    const int warp_m = wid & 3, warp_n = wid >> 2;
    const int m0 = blockIdx.y * 128, n0g = blockIdx.x * 128;
    const int p = (MODE == 0) ? (n0g >> 10) : 0;
    const int hd_off = (MODE == 0) ? (n0g & 1023) : n0g;
    const float* bp = (MODE == 0) ? (p == 0 ? bb0 : (p == 1 ? bb1 : bb2)) : bb0;
    const u8* A = (MODE == 0) ? g_x8 : g_attn8;
    const u8* W = (MODE == 0) ? g_w8 : g_wo8;

    if (tid < 128) sbias[tid] = bp[hd_off + tid];

    float acc[2][8][4];
#pragma unroll
    for (int fm = 0; fm < 2; fm++)
#pragma unroll
        for (int fn = 0; fn < 8; fn++)
#pragma unroll
            for (int e = 0; e < 4; e++) acc[fm][fn][e] = 0.0f;

    const u32 sA = smem_u32(As), sB = smem_u32(Bs);
    const int ld_row = tid >> 3, ld_seg = tid & 7;
    const u32 ld_so = SW128((u32)(ld_row * 128 + ld_seg * 16));

    // A frags: matrices = (rows 0-7 / 8-15) x (k16B-half 0/1) of each fm 16-row tile
    const int a_row = warp_m * 32 + (lane & 15);        // (lane>>3&1)*8 + lane&7
    const u32 a_off0 = (u32)a_row * 128;
    const u32 a_kx = (u32)((lane >> 4) << 4);           // 16B k-half
    const u32 a_sw = (u32)(a_row & 7) << 4;
    // B frags: matrices = (n8 pair) x (k16B-half)
    const int b_rin = lane & 7;
    const int b_nadd = ((lane >> 4) & 1) * 8;
    const u32 b_kx = (u32)(((lane >> 3) & 1) << 4);
    const u32 b_sw = (u32)b_rin << 4;
    u32 b_off[4];
#pragma unroll
    for (int g = 0; g < 4; g++)
        b_off[g] = (u32)(warp_n * 64 + g * 16 + b_nadd + b_rin) * 128;

    auto load_stage = [&](int c, int st) {
        const int k0 = c * 128;                          // bytes (= elems)
        const u32 aB = sA + (u32)st * 16384 + ld_so;
        const u32 bB = sB + (u32)st * 16384 + ld_so;
#pragma unroll
        for (int i = 0; i < 4; i++) {
            int row = ld_row + i * 32;
            cp16(aB + (u32)(i * 32 * 128), A + (size_t)(m0 + row) * DM + k0 + ld_seg * 16);
            cp16(bB + (u32)(i * 32 * 128), W + (size_t)(n0g + row) * DM + k0 + ld_seg * 16);
        }
        cp_commit();
    };

    load_stage(0, 0);
    load_stage(1, 1);

    const int NCH = 8;
    int st = 0;
    for (int c = 0; c < NCH; c++) {
        if (c < NCH - 1) cp_wait<1>(); else cp_wait<0>();
        __syncthreads();

        const u32 soff = (u32)st * 16384;
        const u32 aBase = sA + soff + a_off0;
        const u32 bBase = sB + soff;
#pragma unroll
        for (int kc = 0; kc < 4; kc++) {                 // k32 each (32B)
            const u32 kb = (u32)(kc * 32);
            u32 af[2][4];
            ldsm_x4(af[0], aBase + ((kb + a_kx) ^ a_sw));
            ldsm_x4(af[1], aBase + 16 * 128 + ((kb + a_kx) ^ a_sw));
            u32 bf[4][4];
#pragma unroll
            for (int g = 0; g < 4; g++)
                ldsm_x4(bf[g], bBase + b_off[g] + ((kb + b_kx) ^ b_sw));
#pragma unroll
            for (int fm = 0; fm < 2; fm++)
#pragma unroll
                for (int fn = 0; fn < 8; fn++)
                    mma16832_fp8(acc[fm][fn], af[fm], &bf[fn >> 1][(fn & 1) * 2]);
        }

        if (c + 2 < NCH) {
            int st2 = st + 2; if (st2 >= 3) st2 -= 3;
            load_stage(c + 2, st2);
        }
        if (++st == 3) st = 0;
    }

    // epilogue: bias + threshold, fused output formats
    const int gr = lane >> 2, gc = lane & 3;
    const int head_base = hd_off >> 6;

#pragma unroll
    for (int fm = 0; fm < 2; fm++) {
#pragma unroll
        for (int half = 0; half < 2; half++) {
            const int row = m0 + warp_m * 32 + fm * 16 + half * 8 + gr;
            const int b = row >> 11, s = row & 2047;

            if (MODE == 0 && p < 2) {
                u64 mask = 0;
#pragma unroll
                for (int fn = 0; fn < 8; fn++) {
                    float c0 = acc[fm][fn][half * 2 + 0] + sbias[warp_n * 64 + fn * 8 + gc * 2];
                    float c1 = acc[fm][fn][half * 2 + 1] + sbias[warp_n * 64 + fn * 8 + gc * 2 + 1];
                    mask |= (u64)(c0 > 0.5f) << (fn * 8 + gc * 2);
                    mask |= (u64)(c1 > 0.5f) << (fn * 8 + gc * 2 + 1);
                }
                mask |= __shfl_xor_sync(0xFFFFFFFFu, mask, 1);
                mask |= __shfl_xor_sync(0xFFFFFFFFu, mask, 2);
                if (gc == 0) {
                    const int h = head_base + warp_n;
                    ((p == 0) ? g_qbits : g_kbits)[((size_t)(b * H_ + h)) * S_ + s] = mask;
                }
            } else if (MODE == 0) {
                const int h = head_base + warp_n;
                __nv_bfloat16* dst = g_vb + (((size_t)(b * H_ + h)) * S_ + s) * HD;
#pragma unroll
                for (int fn = 0; fn < 8; fn++) {
                    float c0 = acc[fm][fn][half * 2 + 0] + sbias[warp_n * 64 + fn * 8 + gc * 2];
                    float c1 = acc[fm][fn][half * 2 + 1] + sbias[warp_n * 64 + fn * 8 + gc * 2 + 1];
                    *(u32*)(dst + fn * 8 + gc * 2) =
                        bf2pack((c0 > 0.5f) ? 1.0f : 0.0f, (c1 > 0.5f) ? 1.0f : 0.0f);
                }
            } else {
                float* dst = out + (size_t)row * DM + n0g + warp_n * 64;
#pragma unroll
                for (int fn = 0; fn < 8; fn++) {
                    float c0 = acc[fm][fn][half * 2 + 0] + sbias[warp_n * 64 + fn * 8 + gc * 2];
                    float c1 = acc[fm][fn][half * 2 + 1] + sbias[warp_n * 64 + fn * 8 + gc * 2 + 1];
                    float2 f; f.x = (c0 > 0.5f) ? 1.0f : 0.0f; f.y = (c1 > 0.5f) ? 1.0f : 0.0f;
                    *(float2*)(dst + fn * 8 + gc * 2) = f;
                }
            }
        }
    }
}

// ---------------- attention: popcount -> P in A-frag regs -> HMMA PV, 3-stage pipeline ----------------
// w2 = e^{cnt/4} = 2^(cnt * 0.25*log2e). out_d = sum w2 v / Z2 (eps term <=2e-5 rel, dropped).
// Output written as e4m3 (values in [0,1]) for the fp8 O-projection.
__global__ void __launch_bounds__(256) attn_kernel() {
    __shared__ __align__(16) u64 kb[3][128];                       // 3 x 1 KB
    __shared__ __align__(16) __nv_bfloat16 Vs[3][128 * HD];        // 3 x 16 KB

    const int tid = threadIdx.x, lane = tid & 31, wid = tid >> 5;
    const int gr = lane >> 2, gc = lane & 3;
    const int h = blockIdx.y, b = blockIdx.z;
    const int bh = b * H_ + h;
    const int q0 = blockIdx.x * 128;

    const u64 qlo = g_qbits[(size_t)bh * S_ + q0 + wid * 16 + gr];
    const u64 qhi = g_qbits[(size_t)bh * S_ + q0 + wid * 16 + gr + 8];

    const u32 sV = smem_u32(Vs), sK = smem_u32(kb);
    const u32 vbase_off = (u32)(lane & 15) * 128;
    u32 boff[4];
    {
        const u32 hi16 = (u32)((lane >> 4) & 1) << 4;
        const u32 swl = (u32)(lane & 7) << 4;
#pragma unroll
        for (int g = 0; g < 4; g++) boff[g] = ((u32)(g * 32) + hi16) ^ swl;
    }
    const int vld_row = tid >> 1, vld_seg = (tid & 1) * 4;

    auto load_stage = [&](int it, int st) {
        const int kt = it * 128;
        if (tid < 64)
            cp16(sK + (u32)st * 1024 + (u32)tid * 16, &g_kbits[(size_t)bh * S_ + kt + tid * 2]);
        const __nv_bfloat16* src = g_vb + ((size_t)bh * S_ + kt) * HD;
        const u32 vB = sV + (u32)st * 16384;
#pragma unroll
        for (int i = 0; i < 4; i++) {
            int seg = vld_seg + i;
            u32 so = ((u32)(seg * 16)) ^ ((u32)(vld_row & 7) << 4);
            cp16(vB + (u32)vld_row * 128 + so, src + vld_row * HD + seg * 8);
        }
        cp_commit();
    };

    float acc[8][4];
#pragma unroll
    for (int j = 0; j < 8; j++)
#pragma unroll
        for (int e = 0; e < 4; e++) acc[j][e] = 0.0f;
    float zlo = 0.0f, zhi = 0.0f;
    const float C2 = 0.36067376022224085f;   // 0.25 * log2(e)

    load_stage(0, 0);
    load_stage(1, 1);

    int st = 0;
    for (int it = 0; it < 16; it++) {
        if (it < 15) cp_wait<1>(); else cp_wait<0>();
        __syncthreads();

        const u64* kbs = kb[st];
        const u32 vbase = sV + (u32)st * 16384 + vbase_off;
#pragma unroll
        for (int ck = 0; ck < 8; ck++) {
            u32 bfr[4][4];
#pragma unroll
            for (int g = 0; g < 4; g++)
                ldsm_x4_t(bfr[g], vbase + (u32)(ck * 2048) + boff[g]);

            ulonglong2 p0 = *(const ulonglong2*)&kbs[ck * 16 + 2 * gc];
            ulonglong2 p1 = *(const ulonglong2*)&kbs[ck * 16 + 8 + 2 * gc];
            float vl0 = ex2((float)__popcll(qlo & p0.x) * C2);
            float vl1 = ex2((float)__popcll(qlo & p0.y) * C2);
            float vh0 = ex2((float)__popcll(qhi & p0.x) * C2);
            float vh1 = ex2((float)__popcll(qhi & p0.y) * C2);
            float vl2 = ex2((float)__popcll(qlo & p1.x) * C2);
            float vl3 = ex2((float)__popcll(qlo & p1.y) * C2);
            float vh2 = ex2((float)__popcll(qhi & p1.x) * C2);
            float vh3 = ex2((float)__popcll(qhi & p1.y) * C2);
            zlo += (vl0 + vl1) + (vl2 + vl3);
            zhi += (vh0 + vh1) + (vh2 + vh3);
            u32 af[4];
            af[0] = bf2pack(vl0, vl1);
            af[1] = bf2pack(vh0, vh1);
            af[2] = bf2pack(vl2, vl3);
            af[3] = bf2pack(vh2, vh3);
#pragma unroll
            for (int g = 0; g < 4; g++) {
                mma16816(acc[2 * g],     af, bfr[g]);
                mma16816(acc[2 * g + 1], af, bfr[g] + 2);
            }
        }

        if (it + 2 < 16) {
            int st2 = st + 2; if (st2 >= 3) st2 -= 3;
            load_stage(it + 2, st2);
        }
        if (++st == 3) st = 0;
    }

    zlo += __shfl_xor_sync(0xFFFFFFFFu, zlo, 1);
    zlo += __shfl_xor_sync(0xFFFFFFFFu, zlo, 2);
    zhi += __shfl_xor_sync(0xFFFFFFFFu, zhi, 1);
    zhi += __shfl_xor_sync(0xFFFFFFFFu, zhi, 2);
    const float il = 1.0f / zlo, ih = 1.0f / zhi;

    const int sq = q0 + wid * 16 + gr;
    u8* dlo = g_attn8 + ((size_t)(b * S_ + sq)) * DM + h * HD;
    u8* dhi = dlo + (size_t)8 * DM;
#pragma unroll
    for (int j = 0; j < 8; j++) {
        u16 plo = (u16)f2e4m3(acc[j][0] * il) | ((u16)f2e4m3(acc[j][1] * il) << 8);
        u16 phi = (u16)f2e4m3(acc[j][2] * ih) | ((u16)f2e4m3(acc[j][3] * ih) << 8);
        *(u16*)(dlo + j * 8 + 2 * gc) = plo;
        *(u16*)(dhi + j * 8 + 2 * gc) = phi;
    }
}

// ---------------- launch ----------------
extern "C" void kernel_launch(void* const* d_in, const int* in_sizes, int n_in,
                              void* d_out, int out_size) {
    const float* x  = (const float*)d_in[0];
    const float* wq = (const float*)d_in[1];
    const float* bq = (const float*)d_in[2];
    const float* wk = (const float*)d_in[3];
    const float* bk = (const float*)d_in[4];
    const float* wv = (const float*)d_in[5];
    const float* bv = (const float*)d_in[6];
    const float* wo = (const float*)d_in[7];
    const float* bo = (const float*)d_in[8];
    float* out = (float*)d_out;

    // fp32 -> e4m3 staging (x + 4 weight matrices)
    convert_kernel<<<(XN + 4 * WN) / 4 / 256, 256>>>(x, wq, wk, wv, wo);

    // fused QKV projection (N = 3072 stacked) -> bit masks / head-major bf16 V
    gemm_mma<0><<<dim3(24, 32), 256>>>(bq, bk, bv, nullptr);

    // attention (HMMA PV, 3-stage pipeline) -> e4m3
    attn_kernel<<<dim3(S_ / 128, H_, B_), 256>>>();

    // output projection -> d_out (fp32 {0,1})
    gemm_mma<1><<<dim3(8, 32), 256>>>(bo, nullptr, nullptr, out);
}

// round 11
// speedup vs baseline: 1.1608x; 1.1608x over previous
#include <cuda_runtime.h>
#include <cuda_bf16.h>
#include <cstdint>

#define B_    2
#define S_    2048
#define DM    1024
#define H_    16
#define HD    64
#define MROWS 4096
#define XN    (MROWS * DM)      // 4194304
#define WN    (DM * DM)         // 1048576

typedef unsigned long long u64;
typedef unsigned int u32;

// ---------------- scratch (device globals; no allocation allowed) ----------------
__device__ __align__(16) __nv_bfloat16 g_xb[XN];          // x in bf16 (8 MB)
__device__ __align__(16) __nv_bfloat16 g_wb[3 * WN];      // wq|wk|wv stacked bf16 (6 MB)
__device__ __align__(16) __nv_bfloat16 g_wob[WN];         // wo bf16 (2 MB)
__device__ __align__(16) u64  g_qbits[B_ * H_ * S_];      // packed Q bits
__device__ __align__(16) u64  g_kbits[B_ * H_ * S_];      // packed K bits
__device__ __align__(16) __nv_bfloat16 g_vb[B_ * H_ * S_ * HD]; // V head-major bf16 (8 MB)
__device__ __align__(16) __nv_bfloat16 g_attnb[XN];       // attention out bf16 (8 MB)

// ---------------- helpers ----------------
__device__ __forceinline__ u32 smem_u32(const void* p) {
    u32 a;
    asm("{ .reg .u64 t; cvta.to.shared.u64 t, %1; cvt.u32.u64 %0, t; }" : "=r"(a) : "l"(p));
    return a;
}
__device__ __forceinline__ void cp16(u32 saddr, const void* gaddr) {
    asm volatile("cp.async.cg.shared.global [%0], [%1], 16;" :: "r"(saddr), "l"(gaddr));
}
__device__ __forceinline__ void cp_commit() { asm volatile("cp.async.commit_group;" ::: "memory"); }
template <int N> __device__ __forceinline__ void cp_wait() {
    asm volatile("cp.async.wait_group %0;" :: "n"(N) : "memory");
}
__device__ __forceinline__ void ldsm_x4(u32* r, u32 addr) {
    asm volatile("ldmatrix.sync.aligned.m8n8.x4.shared.b16 {%0,%1,%2,%3}, [%4];"
        : "=r"(r[0]), "=r"(r[1]), "=r"(r[2]), "=r"(r[3]) : "r"(addr));
}
__device__ __forceinline__ void ldsm_x4_t(u32* r, u32 addr) {
    asm volatile("ldmatrix.sync.aligned.m8n8.x4.trans.shared.b16 {%0,%1,%2,%3}, [%4];"
        : "=r"(r[0]), "=r"(r[1]), "=r"(r[2]), "=r"(r[3]) : "r"(addr));
}
__device__ __forceinline__ void mma16816(float* c, const u32* a, const u32* b) {
    asm volatile("mma.sync.aligned.m16n8k16.row.col.f32.bf16.bf16.f32 "
        "{%0,%1,%2,%3}, {%4,%5,%6,%7}, {%8,%9}, {%0,%1,%2,%3};"
        : "+f"(c[0]), "+f"(c[1]), "+f"(c[2]), "+f"(c[3])
        : "r"(a[0]), "r"(a[1]), "r"(a[2]), "r"(a[3]), "r"(b[0]), "r"(b[1]));
}
__device__ __forceinline__ u32 bf2pack(float a, float b) {
    __nv_bfloat162 t = __floats2bfloat162_rn(a, b);
    return *(u32*)&t;
}
#define SW128(o) ((o) ^ ((((u32)(o)) >> 3) & 0x70))

// ---------------- fp32 -> bf16 conversion of x and all weights ----------------
__global__ void __launch_bounds__(256) convert_kernel(const float* __restrict__ x,
                                                      const float* __restrict__ wq,
                                                      const float* __restrict__ wk,
                                                      const float* __restrict__ wv,
                                                      const float* __restrict__ wo) {
    size_t i = ((size_t)blockIdx.x * blockDim.x + threadIdx.x) * 4;
    const float* src;
    __nv_bfloat16* dst;
    size_t off;
    if (i < XN) { src = x; dst = g_xb; off = i; }
    else {
        size_t j = i - XN;
        int w = (int)(j >> 20);
        off = j & (WN - 1);
        src = (w == 0) ? wq : (w == 1) ? wk : (w == 2) ? wv : wo;
        dst = (w < 3) ? (g_wb + (size_t)w * WN) : g_wob;
    }
    float4 v = *(const float4*)(src + off);
    __nv_bfloat162 lo = __floats2bfloat162_rn(v.x, v.y);
    __nv_bfloat162 hi = __floats2bfloat162_rn(v.z, v.w);
    uint2 pk;
    pk.x = *(u32*)&lo; pk.y = *(u32*)&hi;
    *(uint2*)(dst + off) = pk;
}

// ---------------- HMMA GEMM: 3-stage cp.async pipeline (bf16) ----------------
// MODE 0: A=g_xb, W=g_wb (3072 N-rows: q|k|v), epilogue -> g_qbits/g_kbits masks, g_vb bf16
// MODE 1: A=g_attnb, W=g_wob, epilogue -> out fp32 {0,1}
template <int MODE>
__global__ void __launch_bounds__(256) gemm_mma(const float* __restrict__ bb0,
                                               const float* __restrict__ bb1,
                                               const float* __restrict__ bb2,
                                               float* __restrict__ out) {
    __shared__ __align__(16) __nv_bfloat16 As[3][128 * 64];   // 3 x 16 KB
    __shared__ __align__(16) __nv_bfloat16 Bs[3][128 * 64];   // 3 x 16 KB
    __shared__ float sbias[128];

    const int tid = threadIdx.x, lane = tid & 31, wid = tid >> 5;
    const int warp_m = wid & 3, warp_n = wid >> 2;
    const int m0 = blockIdx.y * 128, n0g = blockIdx.x * 128;
    const int p = (MODE == 0) ? (n0g >> 10) : 0;
    const int hd_off = (MODE == 0) ? (n0g & 1023) : n0g;
    const float* bp = (MODE == 0) ? (p == 0 ? bb0 : (p == 1 ? bb1 : bb2)) : bb0;
    const __nv_bfloat16* A = (MODE == 0) ? g_xb : g_attnb;
    const __nv_bfloat16* W = (MODE == 0) ? g_wb : g_wob;

    if (tid < 128) sbias[tid] = bp[hd_off + tid];

    float acc[2][8][4];
#pragma unroll
    for (int fm = 0; fm < 2; fm++)
#pragma unroll
        for (int fn = 0; fn < 8; fn++)
#pragma unroll
            for (int e = 0; e < 4; e++) acc[fm][fn][e] = 0.0f;

    const u32 sA = smem_u32(As), sB = smem_u32(Bs);
    const int ld_row = tid >> 3, ld_seg = tid & 7;
    const u32 ld_so = SW128((u32)(ld_row * 128 + ld_seg * 16));

    const int a_row = warp_m * 32 + (lane & 15);
    const u32 a_off0 = (u32)a_row * 128;
    const u32 a_kx = (u32)((lane >> 4) << 4);
    const u32 a_sw = (u32)(a_row & 7) << 4;
    const int b_rin = lane & 7;
    const int b_nadd = ((lane >> 4) & 1) * 8;
    const u32 b_kx = (u32)(((lane >> 3) & 1) << 4);
    const u32 b_sw = (u32)b_rin << 4;
    u32 b_off[4];
#pragma unroll
    for (int g = 0; g < 4; g++)
        b_off[g] = (u32)(warp_n * 64 + g * 16 + b_nadd + b_rin) * 128;

    auto load_stage = [&](int c, int st) {
        const int k0 = c * 64;
        const u32 aB = sA + (u32)st * 16384 + ld_so;
        const u32 bB = sB + (u32)st * 16384 + ld_so;
#pragma unroll
        for (int i = 0; i < 4; i++) {
            int row = ld_row + i * 32;
            cp16(aB + (u32)(i * 32 * 128), A + (size_t)(m0 + row) * DM + k0 + ld_seg * 8);
            cp16(bB + (u32)(i * 32 * 128), W + (size_t)(n0g + row) * DM + k0 + ld_seg * 8);
        }
        cp_commit();
    };

    load_stage(0, 0);
    load_stage(1, 1);

    int st = 0;
    for (int c = 0; c < 16; c++) {
        if (c < 15) cp_wait<1>(); else cp_wait<0>();
        __syncthreads();

        const u32 soff = (u32)st * 16384;
        const u32 aBase = sA + soff + a_off0;
        const u32 bBase = sB + soff;
#pragma unroll
        for (int kc = 0; kc < 4; kc++) {
            const u32 kb = (u32)(kc * 32);
            u32 af[2][4];
            ldsm_x4(af[0], aBase + ((kb + a_kx) ^ a_sw));
            ldsm_x4(af[1], aBase + 16 * 128 + ((kb + a_kx) ^ a_sw));
            u32 bf[4][4];
#pragma unroll
            for (int g = 0; g < 4; g++)
                ldsm_x4(bf[g], bBase + b_off[g] + ((kb + b_kx) ^ b_sw));
#pragma unroll
            for (int fm = 0; fm < 2; fm++)
#pragma unroll
                for (int fn = 0; fn < 8; fn++)
                    mma16816(acc[fm][fn], af[fm], &bf[fn >> 1][(fn & 1) * 2]);
        }

        if (c + 2 < 16) {
            int st2 = st + 2; if (st2 >= 3) st2 -= 3;
            load_stage(c + 2, st2);
        }
        if (++st == 3) st = 0;
    }

    // epilogue: bias + threshold, fused output formats
    const int gr = lane >> 2, gc = lane & 3;
    const int head_base = hd_off >> 6;

#pragma unroll
    for (int fm = 0; fm < 2; fm++) {
#pragma unroll
        for (int half = 0; half < 2; half++) {
            const int row = m0 + warp_m * 32 + fm * 16 + half * 8 + gr;
            const int b = row >> 11, s = row & 2047;

            if (MODE == 0 && p < 2) {
                u64 mask = 0;
#pragma unroll
                for (int fn = 0; fn < 8; fn++) {
                    float c0 = acc[fm][fn][half * 2 + 0] + sbias[warp_n * 64 + fn * 8 + gc * 2];
                    float c1 = acc[fm][fn][half * 2 + 1] + sbias[warp_n * 64 + fn * 8 + gc * 2 + 1];
                    mask |= (u64)(c0 > 0.5f) << (fn * 8 + gc * 2);
                    mask |= (u64)(c1 > 0.5f) << (fn * 8 + gc * 2 + 1);
                }
                mask |= __shfl_xor_sync(0xFFFFFFFFu, mask, 1);
                mask |= __shfl_xor_sync(0xFFFFFFFFu, mask, 2);
                if (gc == 0) {
                    const int h = head_base + warp_n;
                    ((p == 0) ? g_qbits : g_kbits)[((size_t)(b * H_ + h)) * S_ + s] = mask;
                }
            } else if (MODE == 0) {
                const int h = head_base + warp_n;
                __nv_bfloat16* dst = g_vb + (((size_t)(b * H_ + h)) * S_ + s) * HD;
#pragma unroll
                for (int fn = 0; fn < 8; fn++) {
                    float c0 = acc[fm][fn][half * 2 + 0] + sbias[warp_n * 64 + fn * 8 + gc * 2];
                    float c1 = acc[fm][fn][half * 2 + 1] + sbias[warp_n * 64 + fn * 8 + gc * 2 + 1];
                    *(u32*)(dst + fn * 8 + gc * 2) =
                        bf2pack((c0 > 0.5f) ? 1.0f : 0.0f, (c1 > 0.5f) ? 1.0f : 0.0f);
                }
            } else {
                float* dst = out + (size_t)row * DM + n0g + warp_n * 64;
#pragma unroll
                for (int fn = 0; fn < 8; fn++) {
                    float c0 = acc[fm][fn][half * 2 + 0] + sbias[warp_n * 64 + fn * 8 + gc * 2];
                    float c1 = acc[fm][fn][half * 2 + 1] + sbias[warp_n * 64 + fn * 8 + gc * 2 + 1];
                    float2 f; f.x = (c0 > 0.5f) ? 1.0f : 0.0f; f.y = (c1 > 0.5f) ? 1.0f : 0.0f;
                    *(float2*)(dst + fn * 8 + gc * 2) = f;
                }
            }
        }
    }
}

// ---------------- attention: popcount -> smem LUT -> P in A-frag regs -> HMMA PV ----------------
// w2[c] = bf16(e^{c/4}) stored as f32 bit pattern (bf16 bits << 16), c in [0,64].
// P frag pack = PRMT of two LUT words' high halves; Z sums the identical bf16-rounded values.
__global__ void __launch_bounds__(256) attn_kernel() {
    __shared__ __align__(16) u64 kb[3][128];                       // 3 x 1 KB
    __shared__ __align__(16) __nv_bfloat16 Vs[3][128 * HD];        // 3 x 16 KB
    __shared__ u32 w2lut[65];

    const int tid = threadIdx.x, lane = tid & 31, wid = tid >> 5;
    const int gr = lane >> 2, gc = lane & 3;
    const int h = blockIdx.y, b = blockIdx.z;
    const int bh = b * H_ + h;
    const int q0 = blockIdx.x * 128;

    if (tid < 65) {
        __nv_bfloat16 w = __float2bfloat16_rn(expf((float)tid * 0.25f));
        w2lut[tid] = ((u32)*(unsigned short*)&w) << 16;
    }

    const u64 qlo = g_qbits[(size_t)bh * S_ + q0 + wid * 16 + gr];
    const u64 qhi = g_qbits[(size_t)bh * S_ + q0 + wid * 16 + gr + 8];

    const u32 sV = smem_u32(Vs), sK = smem_u32(kb);
    const u32 vbase_off = (u32)(lane & 15) * 128;
    u32 boff[4];
    {
        const u32 hi16 = (u32)((lane >> 4) & 1) << 4;
        const u32 swl = (u32)(lane & 7) << 4;
#pragma unroll
        for (int g = 0; g < 4; g++) boff[g] = ((u32)(g * 32) + hi16) ^ swl;
    }
    const int vld_row = tid >> 1, vld_seg = (tid & 1) * 4;

    auto load_stage = [&](int it, int st) {
        const int kt = it * 128;
        if (tid < 64)
            cp16(sK + (u32)st * 1024 + (u32)tid * 16, &g_kbits[(size_t)bh * S_ + kt + tid * 2]);
        const __nv_bfloat16* src = g_vb + ((size_t)bh * S_ + kt) * HD;
        const u32 vB = sV + (u32)st * 16384;
#pragma unroll
        for (int i = 0; i < 4; i++) {
            int seg = vld_seg + i;
            u32 so = ((u32)(seg * 16)) ^ ((u32)(vld_row & 7) << 4);
            cp16(vB + (u32)vld_row * 128 + so, src + vld_row * HD + seg * 8);
        }
        cp_commit();
    };

    float acc[8][4];
#pragma unroll
    for (int j = 0; j < 8; j++)
#pragma unroll
        for (int e = 0; e < 4; e++) acc[j][e] = 0.0f;
    float zlo = 0.0f, zhi = 0.0f;

    load_stage(0, 0);
    load_stage(1, 1);

    int st = 0;
    for (int it = 0; it < 16; it++) {
        if (it < 15) cp_wait<1>(); else cp_wait<0>();
        __syncthreads();

        const u64* kbs = kb[st];
        const u32 vbase = sV + (u32)st * 16384 + vbase_off;
#pragma unroll
        for (int ck = 0; ck < 8; ck++) {
            // hoist V fragments: LDSM latency hides under the P-generation work below
            u32 bfr[4][4];
#pragma unroll
            for (int g = 0; g < 4; g++)
                ldsm_x4_t(bfr[g], vbase + (u32)(ck * 2048) + boff[g]);

            ulonglong2 p0 = *(const ulonglong2*)&kbs[ck * 16 + 2 * gc];
            ulonglong2 p1 = *(const ulonglong2*)&kbs[ck * 16 + 8 + 2 * gc];
            u32 l0 = w2lut[__popcll(qlo & p0.x)];
            u32 l1 = w2lut[__popcll(qlo & p0.y)];
            u32 h0 = w2lut[__popcll(qhi & p0.x)];
            u32 h1 = w2lut[__popcll(qhi & p0.y)];
            u32 l2 = w2lut[__popcll(qlo & p1.x)];
            u32 l3 = w2lut[__popcll(qlo & p1.y)];
            u32 h2 = w2lut[__popcll(qhi & p1.x)];
            u32 h3 = w2lut[__popcll(qhi & p1.y)];
            zlo += (__int_as_float(l0) + __int_as_float(l1))
                 + (__int_as_float(l2) + __int_as_float(l3));
            zhi += (__int_as_float(h0) + __int_as_float(h1))
                 + (__int_as_float(h2) + __int_as_float(h3));
            u32 af[4];
            af[0] = __byte_perm(l0, l1, 0x7632);   // (row gr,   k 2gc,2gc+1)
            af[1] = __byte_perm(h0, h1, 0x7632);   // (row gr+8, k 2gc,2gc+1)
            af[2] = __byte_perm(l2, l3, 0x7632);   // (row gr,   k 8+2gc,+1)
            af[3] = __byte_perm(h2, h3, 0x7632);   // (row gr+8, k 8+2gc,+1)
#pragma unroll
            for (int g = 0; g < 4; g++) {
                mma16816(acc[2 * g],     af, bfr[g]);
                mma16816(acc[2 * g + 1], af, bfr[g] + 2);
            }
        }

        if (it + 2 < 16) {
            int st2 = st + 2; if (st2 >= 3) st2 -= 3;
            load_stage(it + 2, st2);
        }
        if (++st == 3) st = 0;
    }

    zlo += __shfl_xor_sync(0xFFFFFFFFu, zlo, 1);
    zlo += __shfl_xor_sync(0xFFFFFFFFu, zlo, 2);
    zhi += __shfl_xor_sync(0xFFFFFFFFu, zhi, 1);
    zhi += __shfl_xor_sync(0xFFFFFFFFu, zhi, 2);
    const float il = 1.0f / zlo, ih = 1.0f / zhi;

    const int sq = q0 + wid * 16 + gr;
    __nv_bfloat16* dlo = g_attnb + ((size_t)(b * S_ + sq)) * DM + h * HD;
    __nv_bfloat16* dhi = dlo + (size_t)8 * DM;
#pragma unroll
    for (int j = 0; j < 8; j++) {
        *(u32*)(dlo + j * 8 + 2 * gc) = bf2pack(acc[j][0] * il, acc[j][1] * il);
        *(u32*)(dhi + j * 8 + 2 * gc) = bf2pack(acc[j][2] * ih, acc[j][3] * ih);
    }
}

// ---------------- launch ----------------
extern "C" void kernel_launch(void* const* d_in, const int* in_sizes, int n_in,
                              void* d_out, int out_size) {
    const float* x  = (const float*)d_in[0];
    const float* wq = (const float*)d_in[1];
    const float* bq = (const float*)d_in[2];
    const float* wk = (const float*)d_in[3];
    const float* bk = (const float*)d_in[4];
    const float* wv = (const float*)d_in[5];
    const float* bv = (const float*)d_in[6];
    const float* wo = (const float*)d_in[7];
    const float* bo = (const float*)d_in[8];
    float* out = (float*)d_out;

    // fp32 -> bf16 staging (x + 4 weight matrices)
    convert_kernel<<<(XN + 4 * WN) / 4 / 256, 256>>>(x, wq, wk, wv, wo);

    // fused QKV projection (N = 3072 stacked) -> bit masks / head-major bf16 V
    gemm_mma<0><<<dim3(24, 32), 256>>>(bq, bk, bv, nullptr);

    // attention (HMMA PV, LUT softmax, 3-stage pipeline)
    attn_kernel<<<dim3(S_ / 128, H_, B_), 256>>>();

    // output projection -> d_out (fp32 {0,1})
    gemm_mma<1><<<dim3(8, 32), 256>>>(bo, nullptr, nullptr, out);
}

// round 12
// speedup vs baseline: 1.1864x; 1.0220x over previous
#include <cuda_runtime.h>
#include <cuda_bf16.h>
#include <cstdint>

#define B_    2
#define S_    2048
#define DM    1024
#define H_    16
#define HD    64
#define MROWS 4096
#define XN    (MROWS * DM)      // 4194304
#define WN    (DM * DM)         // 1048576

typedef unsigned long long u64;
typedef unsigned int u32;

// ---------------- scratch (device globals; no allocation allowed) ----------------
__device__ __align__(16) __nv_bfloat16 g_xb[XN];          // x in bf16 (8 MB)
__device__ __align__(16) __nv_bfloat16 g_wb[3 * WN];      // wq|wk|wv stacked bf16 (6 MB)
__device__ __align__(16) __nv_bfloat16 g_wob[WN];         // wo bf16 (2 MB)
__device__ __align__(16) u64  g_qbits[B_ * H_ * S_];      // packed Q bits
__device__ __align__(16) u64  g_kbits[B_ * H_ * S_];      // packed K bits
__device__ __align__(16) __nv_bfloat16 g_vb[B_ * H_ * S_ * HD]; // V head-major bf16 (8 MB)
__device__ __align__(16) __nv_bfloat16 g_attnb[XN];       // attention out bf16 (8 MB)

// ---------------- helpers ----------------
__device__ __forceinline__ u32 smem_u32(const void* p) {
    u32 a;
    asm("{ .reg .u64 t; cvta.to.shared.u64 t, %1; cvt.u32.u64 %0, t; }" : "=r"(a) : "l"(p));
    return a;
}
__device__ __forceinline__ void cp16(u32 saddr, const void* gaddr) {
    asm volatile("cp.async.cg.shared.global [%0], [%1], 16;" :: "r"(saddr), "l"(gaddr));
}
__device__ __forceinline__ void cp_commit() { asm volatile("cp.async.commit_group;" ::: "memory"); }
template <int N> __device__ __forceinline__ void cp_wait() {
    asm volatile("cp.async.wait_group %0;" :: "n"(N) : "memory");
}
__device__ __forceinline__ void ldsm_x4(u32* r, u32 addr) {
    asm volatile("ldmatrix.sync.aligned.m8n8.x4.shared.b16 {%0,%1,%2,%3}, [%4];"
        : "=r"(r[0]), "=r"(r[1]), "=r"(r[2]), "=r"(r[3]) : "r"(addr));
}
__device__ __forceinline__ void ldsm_x4_t(u32* r, u32 addr) {
    asm volatile("ldmatrix.sync.aligned.m8n8.x4.trans.shared.b16 {%0,%1,%2,%3}, [%4];"
        : "=r"(r[0]), "=r"(r[1]), "=r"(r[2]), "=r"(r[3]) : "r"(addr));
}
__device__ __forceinline__ void mma16816(float* c, const u32* a, const u32* b) {
    asm volatile("mma.sync.aligned.m16n8k16.row.col.f32.bf16.bf16.f32 "
        "{%0,%1,%2,%3}, {%4,%5,%6,%7}, {%8,%9}, {%0,%1,%2,%3};"
        : "+f"(c[0]), "+f"(c[1]), "+f"(c[2]), "+f"(c[3])
        : "r"(a[0]), "r"(a[1]), "r"(a[2]), "r"(a[3]), "r"(b[0]), "r"(b[1]));
}
__device__ __forceinline__ u32 bf2pack(float a, float b) {
    __nv_bfloat162 t = __floats2bfloat162_rn(a, b);
    return *(u32*)&t;
}
#define SW128(o) ((o) ^ ((((u32)(o)) >> 3) & 0x70))

// ---------------- fp32 -> bf16 conversion of x and all weights ----------------
__global__ void __launch_bounds__(256) convert_kernel(const float* __restrict__ x,
                                                      const float* __restrict__ wq,
                                                      const float* __restrict__ wk,
                                                      const float* __restrict__ wv,
                                                      const float* __restrict__ wo) {
    size_t i = ((size_t)blockIdx.x * blockDim.x + threadIdx.x) * 4;
    const float* src;
    __nv_bfloat16* dst;
    size_t off;
    if (i < XN) { src = x; dst = g_xb; off = i; }
    else {
        size_t j = i - XN;
        int w = (int)(j >> 20);
        off = j & (WN - 1);
        src = (w == 0) ? wq : (w == 1) ? wk : (w == 2) ? wv : wo;
        dst = (w < 3) ? (g_wb + (size_t)w * WN) : g_wob;
    }
    float4 v = *(const float4*)(src + off);
    __nv_bfloat162 lo = __floats2bfloat162_rn(v.x, v.y);
    __nv_bfloat162 hi = __floats2bfloat162_rn(v.z, v.w);
    uint2 pk;
    pk.x = *(u32*)&lo; pk.y = *(u32*)&hi;
    *(uint2*)(dst + off) = pk;
}

// ---------------- HMMA GEMM: 3-stage cp.async pipeline (bf16) ----------------
// MODE 0: A=g_xb, W=g_wb (3072 N-rows: q|k|v), epilogue -> g_qbits/g_kbits masks, g_vb bf16
// MODE 1: A=g_attnb, W=g_wob, epilogue -> out fp32 {0,1}
template <int MODE>
__global__ void __launch_bounds__(256) gemm_mma(const float* __restrict__ bb0,
                                               const float* __restrict__ bb1,
                                               const float* __restrict__ bb2,
                                               float* __restrict__ out) {
    __shared__ __align__(16) __nv_bfloat16 As[3][128 * 64];   // 3 x 16 KB
    __shared__ __align__(16) __nv_bfloat16 Bs[3][128 * 64];   // 3 x 16 KB
    __shared__ float sbias[128];

    const int tid = threadIdx.x, lane = tid & 31, wid = tid >> 5;
    const int warp_m = wid & 3, warp_n = wid >> 2;
    const int m0 = blockIdx.y * 128, n0g = blockIdx.x * 128;
    const int p = (MODE == 0) ? (n0g >> 10) : 0;
    const int hd_off = (MODE == 0) ? (n0g & 1023) : n0g;
    const float* bp = (MODE == 0) ? (p == 0 ? bb0 : (p == 1 ? bb1 : bb2)) : bb0;
    const __nv_bfloat16* A = (MODE == 0) ? g_xb : g_attnb;
    const __nv_bfloat16* W = (MODE == 0) ? g_wb : g_wob;

    if (tid < 128) sbias[tid] = bp[hd_off + tid];

    float acc[2][8][4];
#pragma unroll
    for (int fm = 0; fm < 2; fm++)
#pragma unroll
        for (int fn = 0; fn < 8; fn++)
#pragma unroll
            for (int e = 0; e < 4; e++) acc[fm][fn][e] = 0.0f;

    const u32 sA = smem_u32(As), sB = smem_u32(Bs);
    const int ld_row = tid >> 3, ld_seg = tid & 7;
    const u32 ld_so = SW128((u32)(ld_row * 128 + ld_seg * 16));

    const int a_row = warp_m * 32 + (lane & 15);
    const u32 a_off0 = (u32)a_row * 128;
    const u32 a_kx = (u32)((lane >> 4) << 4);
    const u32 a_sw = (u32)(a_row & 7) << 4;
    const int b_rin = lane & 7;
    const int b_nadd = ((lane >> 4) & 1) * 8;
    const u32 b_kx = (u32)(((lane >> 3) & 1) << 4);
    const u32 b_sw = (u32)b_rin << 4;
    u32 b_off[4];
#pragma unroll
    for (int g = 0; g < 4; g++)
        b_off[g] = (u32)(warp_n * 64 + g * 16 + b_nadd + b_rin) * 128;

    auto load_stage = [&](int c, int st) {
        const int k0 = c * 64;
        const u32 aB = sA + (u32)st * 16384 + ld_so;
        const u32 bB = sB + (u32)st * 16384 + ld_so;
#pragma unroll
        for (int i = 0; i < 4; i++) {
            int row = ld_row + i * 32;
            cp16(aB + (u32)(i * 32 * 128), A + (size_t)(m0 + row) * DM + k0 + ld_seg * 8);
            cp16(bB + (u32)(i * 32 * 128), W + (size_t)(n0g + row) * DM + k0 + ld_seg * 8);
        }
        cp_commit();
    };

    load_stage(0, 0);
    load_stage(1, 1);

    int st = 0;
    for (int c = 0; c < 16; c++) {
        if (c < 15) cp_wait<1>(); else cp_wait<0>();
        __syncthreads();

        const u32 soff = (u32)st * 16384;
        const u32 aBase = sA + soff + a_off0;
        const u32 bBase = sB + soff;
#pragma unroll
        for (int kc = 0; kc < 4; kc++) {
            const u32 kb = (u32)(kc * 32);
            u32 af[2][4];
            ldsm_x4(af[0], aBase + ((kb + a_kx) ^ a_sw));
            ldsm_x4(af[1], aBase + 16 * 128 + ((kb + a_kx) ^ a_sw));
            u32 bf[4][4];
#pragma unroll
            for (int g = 0; g < 4; g++)
                ldsm_x4(bf[g], bBase + b_off[g] + ((kb + b_kx) ^ b_sw));
#pragma unroll
            for (int fm = 0; fm < 2; fm++)
#pragma unroll
                for (int fn = 0; fn < 8; fn++)
                    mma16816(acc[fm][fn], af[fm], &bf[fn >> 1][(fn & 1) * 2]);
        }

        if (c + 2 < 16) {
            int st2 = st + 2; if (st2 >= 3) st2 -= 3;
            load_stage(c + 2, st2);
        }
        if (++st == 3) st = 0;
    }

    // epilogue: bias + threshold, fused output formats
    const int gr = lane >> 2, gc = lane & 3;
    const int head_base = hd_off >> 6;

#pragma unroll
    for (int fm = 0; fm < 2; fm++) {
#pragma unroll
        for (int half = 0; half < 2; half++) {
            const int row = m0 + warp_m * 32 + fm * 16 + half * 8 + gr;
            const int b = row >> 11, s = row & 2047;

            if (MODE == 0 && p < 2) {
                u64 mask = 0;
#pragma unroll
                for (int fn = 0; fn < 8; fn++) {
                    float c0 = acc[fm][fn][half * 2 + 0] + sbias[warp_n * 64 + fn * 8 + gc * 2];
                    float c1 = acc[fm][fn][half * 2 + 1] + sbias[warp_n * 64 + fn * 8 + gc * 2 + 1];
                    mask |= (u64)(c0 > 0.5f) << (fn * 8 + gc * 2);
                    mask |= (u64)(c1 > 0.5f) << (fn * 8 + gc * 2 + 1);
                }
                mask |= __shfl_xor_sync(0xFFFFFFFFu, mask, 1);
                mask |= __shfl_xor_sync(0xFFFFFFFFu, mask, 2);
                if (gc == 0) {
                    const int h = head_base + warp_n;
                    ((p == 0) ? g_qbits : g_kbits)[((size_t)(b * H_ + h)) * S_ + s] = mask;
                }
            } else if (MODE == 0) {
                const int h = head_base + warp_n;
                __nv_bfloat16* dst = g_vb + (((size_t)(b * H_ + h)) * S_ + s) * HD;
#pragma unroll
                for (int fn = 0; fn < 8; fn++) {
                    float c0 = acc[fm][fn][half * 2 + 0] + sbias[warp_n * 64 + fn * 8 + gc * 2];
                    float c1 = acc[fm][fn][half * 2 + 1] + sbias[warp_n * 64 + fn * 8 + gc * 2 + 1];
                    *(u32*)(dst + fn * 8 + gc * 2) =
                        bf2pack((c0 > 0.5f) ? 1.0f : 0.0f, (c1 > 0.5f) ? 1.0f : 0.0f);
                }
            } else {
                float* dst = out + (size_t)row * DM + n0g + warp_n * 64;
#pragma unroll
                for (int fn = 0; fn < 8; fn++) {
                    float c0 = acc[fm][fn][half * 2 + 0] + sbias[warp_n * 64 + fn * 8 + gc * 2];
                    float c1 = acc[fm][fn][half * 2 + 1] + sbias[warp_n * 64 + fn * 8 + gc * 2 + 1];
                    float2 f; f.x = (c0 > 0.5f) ? 1.0f : 0.0f; f.y = (c1 > 0.5f) ? 1.0f : 0.0f;
                    *(float2*)(dst + fn * 8 + gc * 2) = f;
                }
            }
        }
    }
}

// ---------------- attention: 128 threads / 4 warps, warp = 32 q rows ----------------
// popcount -> replicated-LUT w2 -> P in A-frag regs -> HMMA PV, 3-stage pipeline.
// w2[c] = bf16(e^{c/4}) as f32 bits; LUT replicated 16x for near-conflict-free LDS.
__global__ void __launch_bounds__(128, 4) attn_kernel() {
    __shared__ __align__(16) u64 kb[3][128];                       // 3 x 1 KB
    __shared__ __align__(16) __nv_bfloat16 Vs[3][128 * HD];        // 3 x 16 KB
    __shared__ u32 w2rep[65 * 16];                                 // 4.16 KB

    const int tid = threadIdx.x, lane = tid & 31, wid = tid >> 5;  // wid 0..3
    const int gr = lane >> 2, gc = lane & 3;
    const int h = blockIdx.y, b = blockIdx.z;
    const int bh = b * H_ + h;
    const int q0 = blockIdx.x * 128;
    const int lrep = lane & 15;

    for (int i = tid; i < 65 * 16; i += 128) {
        __nv_bfloat16 w = __float2bfloat16_rn(expf((float)(i >> 4) * 0.25f));
        w2rep[i] = ((u32)*(unsigned short*)&w) << 16;
    }

    u64 q[2][2];
#pragma unroll
    for (int fm = 0; fm < 2; fm++)
#pragma unroll
        for (int hf = 0; hf < 2; hf++)
            q[fm][hf] = g_qbits[(size_t)bh * S_ + q0 + wid * 32 + fm * 16 + hf * 8 + gr];

    const u32 sV = smem_u32(Vs), sK = smem_u32(kb);
    const u32 vbase_off = (u32)(lane & 15) * 128;
    u32 boff[4];
    {
        const u32 hi16 = (u32)((lane >> 4) & 1) << 4;
        const u32 swl = (u32)(lane & 7) << 4;
#pragma unroll
        for (int g = 0; g < 4; g++) boff[g] = ((u32)(g * 32) + hi16) ^ swl;
    }
    const int vld_row0 = tid >> 3, vld_seg = tid & 7;   // + i*16 rows, 8 iters

    auto load_stage = [&](int it, int st) {
        const int kt = it * 128;
        if (tid < 64)
            cp16(sK + (u32)st * 1024 + (u32)tid * 16, &g_kbits[(size_t)bh * S_ + kt + tid * 2]);
        const __nv_bfloat16* src = g_vb + ((size_t)bh * S_ + kt) * HD;
        const u32 vB = sV + (u32)st * 16384;
        const u32 so = ((u32)(vld_seg * 16)) ^ ((u32)(vld_row0 & 7) << 4);
#pragma unroll
        for (int i = 0; i < 8; i++) {
            int row = vld_row0 + i * 16;
            cp16(vB + (u32)row * 128 + so, src + row * HD + vld_seg * 8);
        }
        cp_commit();
    };

    float acc[2][8][4];
#pragma unroll
    for (int fm = 0; fm < 2; fm++)
#pragma unroll
        for (int j = 0; j < 8; j++)
#pragma unroll
            for (int e = 0; e < 4; e++) acc[fm][j][e] = 0.0f;
    float z[2][2] = {{0.0f, 0.0f}, {0.0f, 0.0f}};

    load_stage(0, 0);
    load_stage(1, 1);

    int st = 0;
    for (int it = 0; it < 16; it++) {
        if (it < 15) cp_wait<1>(); else cp_wait<0>();
        __syncthreads();

        const u64* kbs = kb[st];
        const u32 vbase = sV + (u32)st * 16384 + vbase_off;
#pragma unroll
        for (int ck = 0; ck < 8; ck++) {
            // hoist V fragments: LDSM latency hides under the P-generation work below
            u32 bfr[4][4];
#pragma unroll
            for (int g = 0; g < 4; g++)
                ldsm_x4_t(bfr[g], vbase + (u32)(ck * 2048) + boff[g]);

            ulonglong2 p0 = *(const ulonglong2*)&kbs[ck * 16 + 2 * gc];
            ulonglong2 p1 = *(const ulonglong2*)&kbs[ck * 16 + 8 + 2 * gc];
#pragma unroll
            for (int fm = 0; fm < 2; fm++) {
                u32 l0 = w2rep[__popcll(q[fm][0] & p0.x) * 16 + lrep];
                u32 l1 = w2rep[__popcll(q[fm][0] & p0.y) * 16 + lrep];
                u32 h0 = w2rep[__popcll(q[fm][1] & p0.x) * 16 + lrep];
                u32 h1 = w2rep[__popcll(q[fm][1] & p0.y) * 16 + lrep];
                u32 l2 = w2rep[__popcll(q[fm][0] & p1.x) * 16 + lrep];
                u32 l3 = w2rep[__popcll(q[fm][0] & p1.y) * 16 + lrep];
                u32 h2 = w2rep[__popcll(q[fm][1] & p1.x) * 16 + lrep];
                u32 h3 = w2rep[__popcll(q[fm][1] & p1.y) * 16 + lrep];
                z[fm][0] += (__int_as_float(l0) + __int_as_float(l1))
                          + (__int_as_float(l2) + __int_as_float(l3));
                z[fm][1] += (__int_as_float(h0) + __int_as_float(h1))
                          + (__int_as_float(h2) + __int_as_float(h3));
                u32 af[4];
                af[0] = __byte_perm(l0, l1, 0x7632);   // (row gr,   k 2gc,2gc+1)
                af[1] = __byte_perm(h0, h1, 0x7632);   // (row gr+8, k 2gc,2gc+1)
                af[2] = __byte_perm(l2, l3, 0x7632);   // (row gr,   k 8+2gc,+1)
                af[3] = __byte_perm(h2, h3, 0x7632);   // (row gr+8, k 8+2gc,+1)
#pragma unroll
                for (int g = 0; g < 4; g++) {
                    mma16816(acc[fm][2 * g],     af, bfr[g]);
                    mma16816(acc[fm][2 * g + 1], af, bfr[g] + 2);
                }
            }
        }

        if (it + 2 < 16) {
            int st2 = st + 2; if (st2 >= 3) st2 -= 3;
            load_stage(it + 2, st2);
        }
        if (++st == 3) st = 0;
    }

#pragma unroll
    for (int fm = 0; fm < 2; fm++) {
        float zl = z[fm][0], zh = z[fm][1];
        zl += __shfl_xor_sync(0xFFFFFFFFu, zl, 1);
        zl += __shfl_xor_sync(0xFFFFFFFFu, zl, 2);
        zh += __shfl_xor_sync(0xFFFFFFFFu, zh, 1);
        zh += __shfl_xor_sync(0xFFFFFFFFu, zh, 2);
        const float il = 1.0f / zl, ih = 1.0f / zh;

        const int sq = q0 + wid * 32 + fm * 16 + gr;
        __nv_bfloat16* dlo = g_attnb + ((size_t)(b * S_ + sq)) * DM + h * HD;
        __nv_bfloat16* dhi = dlo + (size_t)8 * DM;
#pragma unroll
        for (int j = 0; j < 8; j++) {
            *(u32*)(dlo + j * 8 + 2 * gc) = bf2pack(acc[fm][j][0] * il, acc[fm][j][1] * il);
            *(u32*)(dhi + j * 8 + 2 * gc) = bf2pack(acc[fm][j][2] * ih, acc[fm][j][3] * ih);
        }
    }
}

// ---------------- launch ----------------
extern "C" void kernel_launch(void* const* d_in, const int* in_sizes, int n_in,
                              void* d_out, int out_size) {
    const float* x  = (const float*)d_in[0];
    const float* wq = (const float*)d_in[1];
    const float* bq = (const float*)d_in[2];
    const float* wk = (const float*)d_in[3];
    const float* bk = (const float*)d_in[4];
    const float* wv = (const float*)d_in[5];
    const float* bv = (const float*)d_in[6];
    const float* wo = (const float*)d_in[7];
    const float* bo = (const float*)d_in[8];
    float* out = (float*)d_out;

    // fp32 -> bf16 staging (x + 4 weight matrices)
    convert_kernel<<<(XN + 4 * WN) / 4 / 256, 256>>>(x, wq, wk, wv, wo);

    // fused QKV projection (N = 3072 stacked) -> bit masks / head-major bf16 V
    gemm_mma<0><<<dim3(24, 32), 256>>>(bq, bk, bv, nullptr);

    // attention (HMMA PV, replicated LUT, 4-warp CTAs, 3-stage pipeline)
    attn_kernel<<<dim3(S_ / 128, H_, B_), 128>>>();

    // output projection -> d_out (fp32 {0,1})
    gemm_mma<1><<<dim3(8, 32), 256>>>(bo, nullptr, nullptr, out);
}